// round 17
// baseline (speedup 1.0000x reference)
#include <cuda_runtime.h>
#include <cuda_fp16.h>
#include <cstdint>
#include <cstddef>

#define EMBED    256
#define HEADS    8
#define LEVELS   4
#define POINTS   4
#define HEAD_DIM 32

// ---------------------------------------------------------------------------
// Scratch (static __device__ globals; runtime allocation is forbidden)
// ---------------------------------------------------------------------------
__device__ __half g_vph [53248 * 256];   // projected value (fp16)
__device__ __half g_wf16[896 * 256];     // wv 0-255 | wo 256-511 | woff 512-767 | wattn 768-895
__device__ __half g_qf16[3712 * 256];    // query fp16
__device__ float  g_qout[3600 * 384];    // offsets (0-255) | logits (256-383)
__device__ __half g_sampf16[3712 * 256]; // sampled out (plain fp16)

// ---------------------------------------------------------------------------
// helpers
// ---------------------------------------------------------------------------
__device__ __forceinline__ uint32_t smem_u32(const void* p) {
    uint32_t a;
    asm("{ .reg .u64 t; cvta.to.shared.u64 t, %1; cvt.u32.u64 %0, t; }"
        : "=r"(a) : "l"(p));
    return a;
}

__device__ __forceinline__ void ldsm4(uint32_t* r, uint32_t addr) {
    asm volatile("ldmatrix.sync.aligned.m8n8.x4.shared.b16 {%0,%1,%2,%3}, [%4];"
                 : "=r"(r[0]), "=r"(r[1]), "=r"(r[2]), "=r"(r[3]) : "r"(addr));
}

__device__ __forceinline__ void mma_f16(float* c, const uint32_t* a,
                                        uint32_t b0, uint32_t b1) {
    asm volatile(
        "mma.sync.aligned.m16n8k16.row.col.f32.f16.f16.f32 "
        "{%0,%1,%2,%3}, {%4,%5,%6,%7}, {%8,%9}, {%0,%1,%2,%3};"
        : "+f"(c[0]), "+f"(c[1]), "+f"(c[2]), "+f"(c[3])
        : "r"(a[0]), "r"(a[1]), "r"(a[2]), "r"(a[3]), "r"(b0), "r"(b1));
}

__device__ __forceinline__ void cp_async16(uint32_t saddr, const void* gaddr) {
    asm volatile("cp.async.cg.shared.global [%0], [%1], 16;"
                 :: "r"(saddr), "l"(gaddr) : "memory");
}
#define CP_ASYNC_COMMIT() asm volatile("cp.async.commit_group;" ::: "memory")
#define CP_ASYNC_WAIT(N)  asm volatile("cp.async.wait_group %0;" :: "n"(N) : "memory")

union Pack8h { uint4 u; __half b[8]; __half2 h2[4]; };

#define SWZ(o) ((o) ^ (((o) >> 3) & 0x70))

// ---------------------------------------------------------------------------
// Convert weights (896 rows) + query (Mq rows) to fp16. Small (~4.6 MB).
// ---------------------------------------------------------------------------
__global__ __launch_bounds__(256)
void cvt_f16(const float* __restrict__ Wv, const float* __restrict__ Wo,
             const float* __restrict__ Woff, const float* __restrict__ Wattn,
             const float* __restrict__ Q,
             __half* __restrict__ Wf, __half* __restrict__ Qf, int Mq)
{
    int t = blockIdx.x * 256 + threadIdx.x;      // one thread per 8 floats
    int total = (896 + Mq) * 32;
    if (t >= total) return;
    int row = t >> 5;
    int s8  = t & 31;
    const float* src;
    __half* dst;
    if (row < 896) {
        if      (row < 256) src = Wv   + (size_t)row * 256 + s8 * 8;
        else if (row < 512) src = Wo   + (size_t)(row - 256) * 256 + s8 * 8;
        else if (row < 768) src = Woff + (size_t)(row - 512) * 256 + s8 * 8;
        else                src = Wattn+ (size_t)(row - 768) * 256 + s8 * 8;
        dst = Wf + (size_t)row * 256 + s8 * 8;
    } else {
        int r3 = row - 896;
        src = Q  + (size_t)r3 * 256 + s8 * 8;
        dst = Qf + (size_t)r3 * 256 + s8 * 8;
    }
    float4 v0 = *(const float4*)(src);
    float4 v1 = *(const float4*)(src + 4);
    Pack8h H;
    H.h2[0] = __floats2half2_rn(v0.x, v0.y);
    H.h2[1] = __floats2half2_rn(v0.z, v0.w);
    H.h2[2] = __floats2half2_rn(v1.x, v1.y);
    H.h2[3] = __floats2half2_rn(v1.z, v1.w);
    *(uint4*)dst = H.u;
}

// ---------------------------------------------------------------------------
// vproj body with fused conversion: Cv[M,256] fp16 = fp16(Vf fp32) @ Wf^T + b.
// smem: A32 staging 32KB (linear fp32, single) | A16 16KB (swizzled, single)
//       | B16 2x16KB (double). cp.async hides the fp32 loads under compute.
// ---------------------------------------------------------------------------
#define VP_A32 0
#define VP_A16 32768
#define VP_B16 49152
#define VP_SMEM 81920

__device__ __forceinline__ void vproj_fused(
    const float* __restrict__ Vf, const __half* __restrict__ Wf,
    const float* __restrict__ bias0, __half* __restrict__ Cv,
    int M, int m0, int n0, char* sm)
{
    const int tid  = threadIdx.x;
    const int lane = tid & 31;
    const int w    = tid >> 5;
    const int wm   = (w & 1) * 64;
    const int wn   = (w >> 1) * 32;
    const uint32_t sb = smem_u32(sm);

    float acc[4][4][4] = {};

    // stage p: fp32 A slab (128 rows x 64 floats) -> linear A32
    auto prefetchA32 = [&](int p) {
        #pragma unroll
        for (int i = 0; i < 8; i++) {
            int idx = tid + i * 256;         // 0..2047 segs of 16B
            int r   = idx >> 4;              // 0..127
            int seg = idx & 15;              // 16 x 4 floats
            int mr  = m0 + r; if (mr >= M) mr = M - 1;   // clamp (rows >= M discarded)
            cp_async16(sb + VP_A32 + (uint32_t)(r * 256 + seg * 16),
                       Vf + (size_t)mr * 256 + p * 64 + seg * 4);
        }
    };

    auto prefetchB = [&](int p, int buf) {
        const uint32_t bbase = sb + VP_B16 + buf * 16384;
        #pragma unroll
        for (int i = 0; i < 4; i++) {
            int idx = tid + i * 256;         // 0..1023
            int r   = idx >> 3;
            int seg = idx & 7;
            cp_async16(bbase + SWZ((uint32_t)(r * 128 + seg * 16)),
                       Wf + ((size_t)(n0 + r) * 256 + p * 64 + seg * 8));
        }
    };

    // A32 (linear fp32) -> A16 (swizzled fp16)
    auto convertA = [&]() {
        const int row  = tid >> 1;
        const int half = tid & 1;
        const char* srcb = sm + VP_A32 + row * 256 + half * 128;
        #pragma unroll
        for (int q = 0; q < 4; q++) {
            float4 v0 = *(const float4*)(srcb + q * 32);
            float4 v1 = *(const float4*)(srcb + q * 32 + 16);
            Pack8h H;
            H.h2[0] = __floats2half2_rn(v0.x, v0.y);
            H.h2[1] = __floats2half2_rn(v0.z, v0.w);
            H.h2[2] = __floats2half2_rn(v1.x, v1.y);
            H.h2[3] = __floats2half2_rn(v1.z, v1.w);
            *(uint4*)(sm + VP_A16 + SWZ((uint32_t)(row * 128 + half * 64 + q * 16))) = H.u;
        }
    };

    auto compute = [&](int buf) {
        const uint32_t abase = sb + VP_A16;
        const uint32_t bbase = sb + VP_B16 + buf * 16384;
        const int j = lane >> 3, r = lane & 7;
        #pragma unroll
        for (int g = 0; g < 4; g++) {
            uint32_t bfr[2][4];
            #pragma unroll
            for (int nt = 0; nt < 2; nt++) {
                uint32_t row  = wn + nt * 16 + (j >> 1) * 8 + r;
                uint32_t colb = (g * 16 + (j & 1) * 8) * 2;
                ldsm4(bfr[nt], bbase + SWZ(row * 128 + colb));
            }
            #pragma unroll
            for (int mt = 0; mt < 4; mt++) {
                uint32_t af[4];
                uint32_t row  = wm + mt * 16 + (j & 1) * 8 + r;
                uint32_t colb = (g * 16 + (j >> 1) * 8) * 2;
                ldsm4(af, abase + SWZ(row * 128 + colb));
                #pragma unroll
                for (int ns = 0; ns < 4; ns++)
                    mma_f16(acc[mt][ns], af,
                            bfr[ns >> 1][(ns & 1) * 2],
                            bfr[ns >> 1][(ns & 1) * 2 + 1]);
            }
        }
    };

    prefetchA32(0);
    prefetchB(0, 0);
    CP_ASYNC_COMMIT();
    #pragma unroll 1
    for (int p = 0; p < 4; p++) {
        int buf = p & 1;
        CP_ASYNC_WAIT(0);
        __syncthreads();
        convertA();              // A32(p) -> A16 ; A32 now free
        __syncthreads();
        if (p + 1 < 4) {
            prefetchA32(p + 1);  // lands during compute(p)
            prefetchB(p + 1, buf ^ 1);
            CP_ASYNC_COMMIT();
        }
        compute(buf);
        __syncthreads();
    }

    const int g = lane >> 2, tig = lane & 3;
    #pragma unroll
    for (int mt = 0; mt < 4; mt++) {
        int mr = m0 + wm + mt * 16 + g;
        #pragma unroll
        for (int ns = 0; ns < 4; ns++) {
            int lc = wn + ns * 8 + tig * 2;
            float bxv = bias0[lc], byv = bias0[lc + 1];
            if (mr < M) {
                __half2 o = __floats2half2_rn(acc[mt][ns][0] + bxv,
                                              acc[mt][ns][1] + byv);
                *(__half2*)&Cv[(size_t)mr * 256 + n0 + lc] = o;
            }
            if (mr + 8 < M) {
                __half2 o = __floats2half2_rn(acc[mt][ns][2] + bxv,
                                              acc[mt][ns][3] + byv);
                *(__half2*)&Cv[(size_t)(mr + 8) * 256 + n0 + lc] = o;
            }
        }
    }
}

// ---------------------------------------------------------------------------
// fp16 MMA GEMM body (both operands already fp16), fp32 output, ldc arbitrary.
// Used for the combined query GEMM.
// ---------------------------------------------------------------------------
__device__ __forceinline__ void mma_gemm_f32out(
    const __half* __restrict__ Af, const __half* __restrict__ Bf,
    const float* __restrict__ bias0, float* __restrict__ C,
    int ldc, int M, int m0, int n0, char* sm)
{
    const int tid  = threadIdx.x;
    const int lane = tid & 31;
    const int w    = tid >> 5;
    const int wm   = (w & 1) * 64;
    const int wn   = (w >> 1) * 32;
    const uint32_t sb = smem_u32(sm);

    float acc[4][4][4] = {};

    auto prefetch = [&](int p, int buf) {
        const uint32_t base = sb + buf * 32768;
        #pragma unroll
        for (int i = 0; i < 8; i++) {
            int idx = tid + i * 256;
            int r   = (idx >> 3) & 127;
            int seg = idx & 7;
            uint32_t so = SWZ((uint32_t)(r * 128 + seg * 16));
            if (idx < 1024) {
                cp_async16(base + so,
                           Af + ((size_t)(m0 + r) * 256 + p * 64 + seg * 8));
            } else {
                cp_async16(base + 16384 + so,
                           Bf + ((size_t)(n0 + r) * 256 + p * 64 + seg * 8));
            }
        }
    };

    auto compute = [&](int buf) {
        const uint32_t abase = sb + buf * 32768;
        const uint32_t bbase = abase + 16384;
        const int j = lane >> 3, r = lane & 7;
        #pragma unroll
        for (int g = 0; g < 4; g++) {
            uint32_t bfr[2][4];
            #pragma unroll
            for (int nt = 0; nt < 2; nt++) {
                uint32_t row  = wn + nt * 16 + (j >> 1) * 8 + r;
                uint32_t colb = (g * 16 + (j & 1) * 8) * 2;
                ldsm4(bfr[nt], bbase + SWZ(row * 128 + colb));
            }
            #pragma unroll
            for (int mt = 0; mt < 4; mt++) {
                uint32_t af[4];
                uint32_t row  = wm + mt * 16 + (j & 1) * 8 + r;
                uint32_t colb = (g * 16 + (j >> 1) * 8) * 2;
                ldsm4(af, abase + SWZ(row * 128 + colb));
                #pragma unroll
                for (int ns = 0; ns < 4; ns++)
                    mma_f16(acc[mt][ns], af,
                            bfr[ns >> 1][(ns & 1) * 2],
                            bfr[ns >> 1][(ns & 1) * 2 + 1]);
            }
        }
    };

    prefetch(0, 0);
    CP_ASYNC_COMMIT();
    #pragma unroll 1
    for (int p = 0; p < 4; p++) {
        int buf = p & 1;
        if (p + 1 < 4) {
            prefetch(p + 1, buf ^ 1);
            CP_ASYNC_COMMIT();
            CP_ASYNC_WAIT(1);
        } else {
            CP_ASYNC_WAIT(0);
        }
        __syncthreads();
        compute(buf);
        __syncthreads();
    }

    const int g = lane >> 2, tig = lane & 3;
    #pragma unroll
    for (int mt = 0; mt < 4; mt++) {
        int mr = m0 + wm + mt * 16 + g;
        #pragma unroll
        for (int ns = 0; ns < 4; ns++) {
            int lc = wn + ns * 8 + tig * 2;
            float bxv = bias0[lc], byv = bias0[lc + 1];
            if (mr < M) {
                float2 o = {acc[mt][ns][0] + bxv, acc[mt][ns][1] + byv};
                *(float2*)&C[(size_t)mr * ldc + n0 + lc] = o;
            }
            if (mr + 8 < M) {
                float2 o = {acc[mt][ns][2] + bxv, acc[mt][ns][3] + byv};
                *(float2*)&C[(size_t)(mr + 8) * ldc + n0 + lc] = o;
            }
        }
    }
}

// ---------------------------------------------------------------------------
// Fat kernel (2 CTAs/SM):
//   blocks [0,87)        : combined query GEMM [Mq,384] fp32 out (87 = 29x3)
//   blocks [87, 87+2MB)  : vproj fused-convert fp16 mma -> fp16 out
// ---------------------------------------------------------------------------
__global__ __launch_bounds__(256, 2)
void fat_gemms(const float* __restrict__ Vf, const __half* __restrict__ Wf,
               const float* __restrict__ b_value,
               __half* __restrict__ Cv, int Mv,
               const __half* __restrict__ Qf,
               const float* __restrict__ b_off, const float* __restrict__ b_attn,
               float* __restrict__ qout, int Mq)
{
    extern __shared__ char sm[];
    const int bx = blockIdx.x;

    if (bx < 87) {
        int mt = bx / 3, nt = bx % 3;
        int n0 = nt * 128;
        const float* bias0 = (n0 < 256) ? b_off + n0 : b_attn;
        mma_gemm_f32out(Qf, Wf + 512 * 256, bias0, qout, 384, Mq,
                        mt * 128, n0, sm);
        return;
    }
    int vb = bx - 87;
    vproj_fused(Vf, Wf, b_value + (vb & 1) * 128, Cv, Mv,
                (vb >> 1) * 128, (vb & 1) * 128, sm);
}

// ---------------------------------------------------------------------------
// Output projection: tile 32x256, single-term fp16 samp, w_out rows 256-511.
// ---------------------------------------------------------------------------
__global__ __launch_bounds__(256)
void outproj_mma32(const __half* __restrict__ Sf, const __half* __restrict__ Wf,
                   const float* __restrict__ b_out, float* __restrict__ C, int Mq)
{
    extern __shared__ char sm[];
    const int tid  = threadIdx.x;
    const int lane = tid & 31;
    const int w    = tid >> 5;
    const int wn   = w * 32;
    const int m0   = blockIdx.x * 32;
    const uint32_t sb = smem_u32(sm);
    const __half* Wo = Wf + 256 * 256;

    float acc[2][4][4] = {};

    auto prefetch = [&](int p, int buf) {
        const uint32_t base = sb + buf * 36864;
        #pragma unroll
        for (int i = 0; i < 9; i++) {
            int idx = tid + i * 256;
            if (idx < 256) {
                int r   = idx >> 3;
                int seg = idx & 7;
                cp_async16(base + SWZ((uint32_t)(r * 128 + seg * 16)),
                           Sf + ((size_t)(m0 + r) * 256 + p * 64 + seg * 8));
            } else {
                int i2  = idx - 256;
                int r   = i2 >> 3;
                int seg = i2 & 7;
                cp_async16(base + 4096 + SWZ((uint32_t)(r * 128 + seg * 16)),
                           Wo + ((size_t)r * 256 + p * 64 + seg * 8));
            }
        }
    };

    auto compute = [&](int buf) {
        const uint32_t abase = sb + buf * 36864;
        const uint32_t bbase = abase + 4096;
        const int j = lane >> 3, r = lane & 7;
        #pragma unroll
        for (int g = 0; g < 4; g++) {
            uint32_t bfr[2][4];
            #pragma unroll
            for (int nt = 0; nt < 2; nt++) {
                uint32_t row  = wn + nt * 16 + (j >> 1) * 8 + r;
                uint32_t colb = (g * 16 + (j & 1) * 8) * 2;
                ldsm4(bfr[nt], bbase + SWZ(row * 128 + colb));
            }
            #pragma unroll
            for (int mt = 0; mt < 2; mt++) {
                uint32_t af[4];
                uint32_t row  = mt * 16 + (j & 1) * 8 + r;
                uint32_t colb = (g * 16 + (j >> 1) * 8) * 2;
                ldsm4(af, abase + SWZ(row * 128 + colb));
                #pragma unroll
                for (int ns = 0; ns < 4; ns++)
                    mma_f16(acc[mt][ns], af,
                            bfr[ns >> 1][(ns & 1) * 2],
                            bfr[ns >> 1][(ns & 1) * 2 + 1]);
            }
        }
    };

    prefetch(0, 0);
    CP_ASYNC_COMMIT();
    #pragma unroll 1
    for (int p = 0; p < 4; p++) {
        int buf = p & 1;
        if (p + 1 < 4) {
            prefetch(p + 1, buf ^ 1);
            CP_ASYNC_COMMIT();
            CP_ASYNC_WAIT(1);
        } else {
            CP_ASYNC_WAIT(0);
        }
        __syncthreads();
        compute(buf);
        __syncthreads();
    }

    const int g = lane >> 2, tig = lane & 3;
    #pragma unroll
    for (int mt = 0; mt < 2; mt++) {
        int mr = m0 + mt * 16 + g;
        #pragma unroll
        for (int ns = 0; ns < 4; ns++) {
            int col = wn + ns * 8 + tig * 2;
            float bxv = b_out[col], byv = b_out[col + 1];
            if (mr < Mq) {
                float2 o = {acc[mt][ns][0] + bxv, acc[mt][ns][1] + byv};
                *(float2*)&C[(size_t)mr * 256 + col] = o;
            }
            if (mr + 8 < Mq) {
                float2 o = {acc[mt][ns][2] + bxv, acc[mt][ns][3] + byv};
                *(float2*)&C[(size_t)(mr + 8) * 256 + col] = o;
            }
        }
    }
}

// ---------------------------------------------------------------------------
// Deformable sampling: 2 queries per block, half2 gathers, plain fp16 output.
// ---------------------------------------------------------------------------
__global__ __launch_bounds__(256)
void msda_sample2(const __half* __restrict__ vproj,
                  const float* __restrict__ refp,
                  const float* __restrict__ qout,
                  const int*   __restrict__ shapes,
                  const int*   __restrict__ lstart,
                  __half* __restrict__ sampf,     // [3712, 256] plain fp16
                  int Lq, int Lv)
{
    const int bq0 = blockIdx.x * 2;
    const int tid = threadIdx.x;
    const int q   = tid >> 7;
    const int c   = tid & 127;

    __shared__ float s_log[2][128];
    __shared__ float s_off[2][256];
    __shared__ float s_ref[2][8];
    __shared__ int   s_shape[8];
    __shared__ int   s_start[4];
    __shared__ int4   s_idx4[2][128];
    __shared__ float4 s_w4[2][128];

    const float* qrow = qout + (size_t)(bq0 + q) * 384;
    s_log[q][c]       = qrow[256 + c];
    s_off[q][c]       = qrow[c];
    s_off[q][c + 128] = qrow[c + 128];
    if (tid < 16) s_ref[tid >> 3][tid & 7] =
        refp[(size_t)(bq0 + (tid >> 3)) * 8 + (tid & 7)];
    if (tid < 8) s_shape[tid] = shapes[tid];
    if (tid < 4) s_start[tid] = lstart[tid];
    __syncthreads();

    {
        const int h = c >> 4;
        const int l = (c >> 2) & 3;

        float mx = -1e30f;
        #pragma unroll
        for (int j = 0; j < 16; j++) mx = fmaxf(mx, s_log[q][h * 16 + j]);
        float sum = 0.f;
        #pragma unroll
        for (int j = 0; j < 16; j++) sum += __expf(s_log[q][h * 16 + j] - mx);
        const float aw = __expf(s_log[q][c] - mx) / sum;

        const int   Hh = s_shape[l * 2 + 0];
        const int   Ww = s_shape[l * 2 + 1];
        const float Wfl = (float)Ww, Hfl = (float)Hh;
        const int   st = s_start[l];
        const float rx = s_ref[q][l * 2 + 0];
        const float ry = s_ref[q][l * 2 + 1];

        const float x = (rx + s_off[q][c * 2 + 0] / Wfl) * Wfl - 0.5f;
        const float y = (ry + s_off[q][c * 2 + 1] / Hfl) * Hfl - 0.5f;
        const float x0f = floorf(x), y0f = floorf(y);
        const float lx = x - x0f, ly = y - y0f;
        const int   x0 = (int)x0f, y0 = (int)y0f;

        const bool vx0 = (x0 >= 0) & (x0 < Ww);
        const bool vx1 = (x0 + 1 >= 0) & (x0 + 1 < Ww);
        const bool vy0 = (y0 >= 0) & (y0 < Hh);
        const bool vy1 = (y0 + 1 >= 0) & (y0 + 1 < Hh);

        int4 id;
        id.x = (vy0 && vx0) ? st + y0 * Ww + x0           : -1;
        id.y = (vy0 && vx1) ? st + y0 * Ww + x0 + 1       : -1;
        id.z = (vy1 && vx0) ? st + (y0 + 1) * Ww + x0     : -1;
        id.w = (vy1 && vx1) ? st + (y0 + 1) * Ww + x0 + 1 : -1;

        float4 ww;
        ww.x = aw * (1.f - lx) * (1.f - ly);
        ww.y = aw * lx * (1.f - ly);
        ww.z = aw * (1.f - lx) * ly;
        ww.w = aw * lx * ly;

        s_idx4[q][c] = id;
        s_w4[q][c]   = ww;
    }
    __syncthreads();

    const int h  = c >> 4;
    const int d2 = c & 15;
    const int bq = bq0 + q;
    const int b  = bq / Lq;
    const __half2* vb = (const __half2*)(vproj + (size_t)b * Lv * EMBED
                                         + h * HEAD_DIM + d2 * 2);

    float2 a0 = {0.f, 0.f}, a1 = {0.f, 0.f}, a2 = {0.f, 0.f}, a3 = {0.f, 0.f};
    #pragma unroll 4
    for (int i = 0; i < 16; i++) {
        const int t = h * 16 + i;
        const int4   id = s_idx4[q][t];
        const float4 ww = s_w4[q][t];
        if (id.x >= 0) {
            float2 f = __half22float2(__ldg(vb + (size_t)id.x * 128));
            a0.x += ww.x * f.x; a0.y += ww.x * f.y;
        }
        if (id.y >= 0) {
            float2 f = __half22float2(__ldg(vb + (size_t)id.y * 128));
            a1.x += ww.y * f.x; a1.y += ww.y * f.y;
        }
        if (id.z >= 0) {
            float2 f = __half22float2(__ldg(vb + (size_t)id.z * 128));
            a2.x += ww.z * f.x; a2.y += ww.z * f.y;
        }
        if (id.w >= 0) {
            float2 f = __half22float2(__ldg(vb + (size_t)id.w * 128));
            a3.x += ww.w * f.x; a3.y += ww.w * f.y;
        }
    }
    const float rx2 = (a0.x + a1.x) + (a2.x + a3.x);
    const float ry2 = (a0.y + a1.y) + (a2.y + a3.y);

    __half2* dst = (__half2*)(sampf + (size_t)bq * 256 + h * HEAD_DIM + d2 * 2);
    *dst = __floats2half2_rn(rx2, ry2);
}

// ---------------------------------------------------------------------------
// kernel_launch
// ---------------------------------------------------------------------------
extern "C" void kernel_launch(void* const* d_in, const int* in_sizes, int n_in,
                              void* d_out, int out_size)
{
    const float* query   = (const float*)d_in[0];
    const float* refp    = (const float*)d_in[1];
    const float* value   = (const float*)d_in[2];
    const int*   shapes  = (const int*)  d_in[3];
    const int*   lstart  = (const int*)  d_in[4];
    const float* w_value = (const float*)d_in[5];
    const float* b_value = (const float*)d_in[6];
    const float* w_off   = (const float*)d_in[7];
    const float* b_off   = (const float*)d_in[8];
    const float* w_attn  = (const float*)d_in[9];
    const float* b_attn  = (const float*)d_in[10];
    const float* w_out   = (const float*)d_in[11];
    const float* b_out   = (const float*)d_in[12];

    const int Mv = in_sizes[2] / EMBED;   // bs * Lv = 53176
    const int Mq = in_sizes[0] / EMBED;   // bs * Lq = 3600
    const int bs = 4;
    const int Lv = Mv / bs;
    const int Lq = Mq / bs;

    float *qoutb;
    __half *vph, *wf, *qf, *sf;
    cudaGetSymbolAddress((void**)&vph,    g_vph);
    cudaGetSymbolAddress((void**)&wf,     g_wf16);
    cudaGetSymbolAddress((void**)&qf,     g_qf16);
    cudaGetSymbolAddress((void**)&qoutb,  g_qout);
    cudaGetSymbolAddress((void**)&sf,     g_sampf16);

    // 1) convert weights + query to fp16 (small)
    {
        int total = (896 + Mq) * 32;
        cvt_f16<<<(total + 255) / 256, 256>>>(w_value, w_out, w_off, w_attn,
                                              query, wf, qf, Mq);
    }

    // 2) fat kernel: query GEMM (87 blocks) + fused-convert vproj (832 blocks)
    const int MB = (Mv + 127) / 128;               // 416
    static bool cfg = false;
    if (!cfg) {
        cudaFuncSetAttribute(fat_gemms,
                             cudaFuncAttributeMaxDynamicSharedMemorySize, VP_SMEM);
        cudaFuncSetAttribute(outproj_mma32,
                             cudaFuncAttributeMaxDynamicSharedMemorySize, 73728);
        cfg = true;
    }
    fat_gemms<<<87 + 2 * MB, 256, VP_SMEM>>>(
        value, wf, b_value, vph, Mv, qf, b_off, b_attn, qoutb, Mq);

    // 3) sampling: 2 queries per block, half2 gathers -> plain fp16
    msda_sample2<<<Mq / 2, 256>>>(vph, refp, qoutb, shapes, lstart,
                                  sf, Lq, Lv);

    // 4) output projection (single-term fp16) -> d_out
    outproj_mma32<<<(Mq + 31) / 32, 256, 73728>>>(sf, wf, b_out,
                                                  (float*)d_out, Mq);
}